// round 10
// baseline (speedup 1.0000x reference)
#include <cuda_runtime.h>
#include <cuda_bf16.h>
#include <cstdint>

#define NN 50000
#define EE 800000
#define HID 64

// ---------------- scratch (__device__ globals; no allocs allowed) ----------
__device__ float g_h[NN * HID];    // gemm1 output, then gather source for agg1
__device__ float g_h2[NN * HID];   // fused (agg1+gemm2) output, gather source for agg2
__device__ int   g_cnt[NN];        // zero at load; re-zeroed by k_fill each run
__device__ int   g_off[NN + 1];
__device__ int   g_cur[NN];
__device__ float g_dinv[NN];
__device__ int   g_csrc[EE];
// Pre-transposed, bf16-split weights: Wt[n][k] (k contiguous)
__device__ uint16_t g_wt1h[64 * 512];
__device__ uint16_t g_wt1l[64 * 512];
__device__ uint16_t g_wt2h[64 * 64];
__device__ uint16_t g_wt2l[64 * 64];

// ---------------- helpers ---------------------------------------------------
__device__ __forceinline__ uint32_t smem_u32(const void* p) {
    uint32_t a;
    asm("{ .reg .u64 t; cvta.to.shared.u64 t, %1; cvt.u32.u64 %0, t; }"
        : "=r"(a) : "l"(p));
    return a;
}
__device__ __forceinline__ uint32_t cvt_bf16x2(float hi_elem, float lo_elem) {
    uint32_t r;
    asm("cvt.rn.bf16x2.f32 %0, %1, %2;" : "=r"(r) : "f"(hi_elem), "f"(lo_elem));
    return r;
}
__device__ __forceinline__ void split_pair(float x0, float x1,
                                           uint32_t& h, uint32_t& l) {
    h = cvt_bf16x2(x1, x0);
    float h0 = __uint_as_float(h << 16);
    float h1 = __uint_as_float(h & 0xffff0000u);
    l = cvt_bf16x2(x1 - h1, x0 - h0);
}
__device__ __forceinline__ void mma_bf16(float& d0, float& d1, float& d2, float& d3,
                                         uint32_t a0, uint32_t a1, uint32_t a2, uint32_t a3,
                                         uint32_t b0, uint32_t b1) {
    asm volatile("mma.sync.aligned.m16n8k16.row.col.f32.bf16.bf16.f32 "
                 "{%0,%1,%2,%3}, {%4,%5,%6,%7}, {%8,%9}, {%0,%1,%2,%3};"
                 : "+f"(d0), "+f"(d1), "+f"(d2), "+f"(d3)
                 : "r"(a0), "r"(a1), "r"(a2), "r"(a3), "r"(b0), "r"(b1));
}
__device__ __forceinline__ void ldsm_x4(uint32_t& r0, uint32_t& r1,
                                        uint32_t& r2, uint32_t& r3, uint32_t addr) {
    asm volatile("ldmatrix.sync.aligned.m8n8.x4.shared.b16 {%0,%1,%2,%3}, [%4];"
                 : "=r"(r0), "=r"(r1), "=r"(r2), "=r"(r3) : "r"(addr));
}

// ---------------- CSR construction -----------------------------------------
__global__ void k_hist(const int* __restrict__ dst) {
    int i = blockIdx.x * blockDim.x + threadIdx.x;
    int base = i * 4;
    if (base >= EE) return;
    int4 d = *(const int4*)(dst + base);
    atomicAdd(&g_cnt[d.x], 1);
    atomicAdd(&g_cnt[d.y], 1);
    atomicAdd(&g_cnt[d.z], 1);
    atomicAdd(&g_cnt[d.w], 1);
}

__global__ void k_scan() {
    extern __shared__ int buf[];
    __shared__ int sm[1024];
    int t = threadIdx.x;
    for (int i = t; i < NN; i += 1024) buf[i] = g_cnt[i];
    __syncthreads();
    const int C = (NN + 1023) / 1024;
    int start = t * C, end = start + C;
    if (end > NN) end = NN;
    int sum = 0;
    for (int i = start; i < end; i++) sum += buf[i];
    sm[t] = sum;
    __syncthreads();
    for (int ofs = 1; ofs < 1024; ofs <<= 1) {
        int v = (t >= ofs) ? sm[t - ofs] : 0;
        __syncthreads();
        sm[t] += v;
        __syncthreads();
    }
    int base = sm[t] - sum;
    for (int i = start; i < end; i++) {
        int c = buf[i];
        buf[i] = base;
        base += c;
        g_dinv[i] = rsqrtf((float)(c + 1));
    }
    __syncthreads();
    for (int i = t; i < NN; i += 1024) {
        int o = buf[i];
        g_off[i] = o;
        g_cur[i] = o;
    }
    if (t == 0) g_off[NN] = EE;
}

// fill CSR (4 edges/thread); also re-zero g_cnt for the next graph replay
__global__ void k_fill(const int* __restrict__ src, const int* __restrict__ dst) {
    int i = blockIdx.x * blockDim.x + threadIdx.x;
    if (i < NN) g_cnt[i] = 0;
    int base = i * 4;
    if (base >= EE) return;
    int4 s4 = *(const int4*)(src + base);
    int4 d4 = *(const int4*)(dst + base);
    g_csrc[atomicAdd(&g_cur[d4.x], 1)] = s4.x;
    g_csrc[atomicAdd(&g_cur[d4.y], 1)] = s4.y;
    g_csrc[atomicAdd(&g_cur[d4.z], 1)] = s4.z;
    g_csrc[atomicAdd(&g_cur[d4.w], 1)] = s4.w;
}

// ------- weight prep: coalesced smem-tile transpose + bf16 split ------------
__global__ void k_prep(const float* __restrict__ W1, const float* __restrict__ W2) {
    __shared__ uint16_t th[32][33], tl[32][33];
    int b = blockIdx.x;
    int tx = threadIdx.x & 31, ty = threadIdx.x >> 5;

    const float* W;
    uint16_t *oh, *ol;
    int kt, ntile, Kd;
    if (b < 32) { W = W1; oh = g_wt1h; ol = g_wt1l; kt = b >> 1; ntile = b & 1; Kd = 512; }
    else        { W = W2; oh = g_wt2h; ol = g_wt2l; kt = (b - 32) >> 1; ntile = (b - 32) & 1; Kd = 64; }

#pragma unroll
    for (int j = 0; j < 4; j++) {
        int k = kt * 32 + ty + j * 8;
        int n = ntile * 32 + tx;
        float v = W[k * 64 + n];
        uint16_t hs = __bfloat16_as_ushort(__float2bfloat16(v));
        float hf = __uint_as_float((uint32_t)hs << 16);
        uint16_t ls = __bfloat16_as_ushort(__float2bfloat16(v - hf));
        th[ty + j * 8][tx] = hs;
        tl[ty + j * 8][tx] = ls;
    }
    __syncthreads();
#pragma unroll
    for (int j = 0; j < 4; j++) {
        int n = ntile * 32 + ty + j * 8;
        int k = kt * 32 + tx;
        oh[n * Kd + k] = th[tx][ty + j * 8];
        ol[n * Kd + k] = tl[tx][ty + j * 8];
    }
}

// ---------------- HMMA bf16-split GEMM (ldmatrix fragments), layer 1 --------
#define XST 40   // smem row stride (uint16): 80B = 5*16B -> LDSM conflict-free

__global__ __launch_bounds__(128, 4) void k_gemm(
    const float* __restrict__ X,
    const uint16_t* __restrict__ Wth, const uint16_t* __restrict__ Wtl,
    float* __restrict__ OUT, int n, int Kdim) {
    __shared__ __align__(16) uint16_t Xh[64 * XST], Xl[64 * XST];
    __shared__ __align__(16) uint16_t Wh[64 * XST], Wl[64 * XST];
    int tid = threadIdx.x;
    int wid = tid >> 5;
    int lane = tid & 31;
    int gid = lane >> 2;
    int q = lane & 3;
    int r0 = blockIdx.x * 64;
    int rb = wid * 16;

    int xrow = tid >> 3;
    int xkg = (tid & 7) * 4;
    int wn = tid >> 4;
    int wkg = tid & 15;

    int g8 = lane >> 3, lr = lane & 7;
    int aoff = (rb + lr + (g8 & 1) * 8) * XST + (g8 >> 1) * 8;
    int boff0 = (lr + (g8 >> 1) * 8) * XST + (g8 & 1) * 8;
    uint32_t xh_b = smem_u32(Xh), xl_b = smem_u32(Xl);
    uint32_t wh_b = smem_u32(Wh), wl_b = smem_u32(Wl);

    const uint32_t* wh32 = (const uint32_t*)Wth;
    const uint32_t* wl32 = (const uint32_t*)Wtl;
    int wstride = Kdim >> 1;

    float acc[8][4];
#pragma unroll
    for (int t = 0; t < 8; t++)
#pragma unroll
        for (int c = 0; c < 4; c++) acc[t][c] = 0.f;

    int nch = Kdim >> 5;
    float4 px[4];
    uint32_t pwh[8], pwl[8];

#pragma unroll
    for (int j = 0; j < 4; j++) {
        int gr = r0 + xrow + j * 16;
        px[j] = (gr < n) ? *(const float4*)(X + (size_t)gr * Kdim + xkg)
                         : make_float4(0.f, 0.f, 0.f, 0.f);
    }
#pragma unroll
    for (int j = 0; j < 8; j++) {
        int nn = wn + j * 8;
        pwh[j] = wh32[nn * wstride + wkg];
        pwl[j] = wl32[nn * wstride + wkg];
    }

    for (int ch = 0; ch < nch; ch++) {
#pragma unroll
        for (int j = 0; j < 4; j++) {
            int row = xrow + j * 16;
            uint32_t h01, l01, h23, l23;
            split_pair(px[j].x, px[j].y, h01, l01);
            split_pair(px[j].z, px[j].w, h23, l23);
            uint32_t* dh = (uint32_t*)&Xh[row * XST + xkg];
            uint32_t* dl = (uint32_t*)&Xl[row * XST + xkg];
            dh[0] = h01; dh[1] = h23;
            dl[0] = l01; dl[1] = l23;
        }
#pragma unroll
        for (int j = 0; j < 8; j++) {
            int nn = wn + j * 8;
            *(uint32_t*)&Wh[nn * XST + wkg * 2] = pwh[j];
            *(uint32_t*)&Wl[nn * XST + wkg * 2] = pwl[j];
        }
        __syncthreads();

        if (ch + 1 < nch) {
            int k0 = (ch + 1) << 5;
#pragma unroll
            for (int j = 0; j < 4; j++) {
                int gr = r0 + xrow + j * 16;
                px[j] = (gr < n)
                    ? *(const float4*)(X + (size_t)gr * Kdim + k0 + xkg)
                    : make_float4(0.f, 0.f, 0.f, 0.f);
            }
#pragma unroll
            for (int j = 0; j < 8; j++) {
                int nn = wn + j * 8;
                pwh[j] = wh32[nn * wstride + (k0 >> 1) + wkg];
                pwl[j] = wl32[nn * wstride + (k0 >> 1) + wkg];
            }
        }

#pragma unroll
        for (int s = 0; s < 2; s++) {
            uint32_t ah[4], al[4];
            ldsm_x4(ah[0], ah[1], ah[2], ah[3], xh_b + 2 * (aoff + s * 16));
            ldsm_x4(al[0], al[1], al[2], al[3], xl_b + 2 * (aoff + s * 16));
#pragma unroll
            for (int p = 0; p < 4; p++) {
                int bo = boff0 + p * 16 * XST + s * 16;
                uint32_t bh[4], bl[4];
                ldsm_x4(bh[0], bh[1], bh[2], bh[3], wh_b + 2 * bo);
                ldsm_x4(bl[0], bl[1], bl[2], bl[3], wl_b + 2 * bo);
                int t0 = 2 * p, t1 = 2 * p + 1;
                mma_bf16(acc[t0][0], acc[t0][1], acc[t0][2], acc[t0][3],
                         ah[0], ah[1], ah[2], ah[3], bh[0], bh[1]);
                mma_bf16(acc[t0][0], acc[t0][1], acc[t0][2], acc[t0][3],
                         ah[0], ah[1], ah[2], ah[3], bl[0], bl[1]);
                mma_bf16(acc[t0][0], acc[t0][1], acc[t0][2], acc[t0][3],
                         al[0], al[1], al[2], al[3], bh[0], bh[1]);
                mma_bf16(acc[t1][0], acc[t1][1], acc[t1][2], acc[t1][3],
                         ah[0], ah[1], ah[2], ah[3], bh[2], bh[3]);
                mma_bf16(acc[t1][0], acc[t1][1], acc[t1][2], acc[t1][3],
                         ah[0], ah[1], ah[2], ah[3], bl[2], bl[3]);
                mma_bf16(acc[t1][0], acc[t1][1], acc[t1][2], acc[t1][3],
                         al[0], al[1], al[2], al[3], bh[2], bh[3]);
            }
        }
        __syncthreads();
    }

    int gr0 = r0 + rb + gid;
    int gr1 = gr0 + 8;
#pragma unroll
    for (int nt = 0; nt < 8; nt++) {
        int col = nt * 8 + 2 * q;
        if (gr0 < n)
            *(float2*)(OUT + (size_t)gr0 * HID + col) =
                make_float2(acc[nt][0], acc[nt][1]);
        if (gr1 < n)
            *(float2*)(OUT + (size_t)gr1 * HID + col) =
                make_float2(acc[nt][2], acc[nt][3]);
    }
}

// ------- FUSED: agg1 + bias + relu -> bf16 split in smem -> GEMM2 -> g_h2 ---
// Block 256 thr (8 warps), 64 nodes. Phase 1: warp aggregates 8 nodes
// (half-warp per edge, float4 per lane). Phase 2: warps 0-3 run 64x64x64 HMMA.
#define FST 72   // 144B row stride = 9*16B -> LDSM conflict-free, holds K=64

__global__ __launch_bounds__(256, 3) void k_fagg(
    const float* __restrict__ H, const float* __restrict__ bias) {
    __shared__ __align__(16) uint16_t Ah[64 * FST], Al[64 * FST];
    __shared__ __align__(16) uint16_t Bh[64 * FST], Bl[64 * FST];
    int tid = threadIdx.x;
    int wid = tid >> 5;
    int lane = tid & 31;
    int r0 = blockIdx.x * 64;

    // stage W2 (already transposed+split): 64 rows x 32 uint32
    const uint32_t* wh32 = (const uint32_t*)g_wt2h;
    const uint32_t* wl32 = (const uint32_t*)g_wt2l;
    for (int idx = tid; idx < 2048; idx += 256) {
        int row = idx >> 5, kk = idx & 31;
        *(uint32_t*)&Bh[row * FST + kk * 2] = wh32[idx];
        *(uint32_t*)&Bl[row * FST + kk * 2] = wl32[idx];
    }

    // phase 1: aggregate act rows into Ah/Al
    int half = lane >> 4;
    int l = (lane & 15) * 4;
    for (int i = 0; i < 8; i++) {
        int row = wid * 8 + i;
        int node = r0 + row;
        float4 a = make_float4(0.f, 0.f, 0.f, 0.f);
        if (node < NN) {
            float di = g_dinv[node];
            if (half == 0) {
                float sw = di * di;
                float4 hv = *(const float4*)(H + (size_t)node * HID + l);
                float4 b = *(const float4*)(bias + l);
                a.x = hv.x * sw + b.x;
                a.y = hv.y * sw + b.y;
                a.z = hv.z * sw + b.z;
                a.w = hv.w * sw + b.w;
            }
            int e1 = g_off[node + 1];
            for (int e = g_off[node] + half; e < e1; e += 2) {
                int s = g_csrc[e];
                float w = g_dinv[s] * di;
                float4 v = *(const float4*)(H + (size_t)s * HID + l);
                a.x += v.x * w;
                a.y += v.y * w;
                a.z += v.z * w;
                a.w += v.w * w;
            }
        }
        a.x += __shfl_xor_sync(0xFFFFFFFFu, a.x, 16);
        a.y += __shfl_xor_sync(0xFFFFFFFFu, a.y, 16);
        a.z += __shfl_xor_sync(0xFFFFFFFFu, a.z, 16);
        a.w += __shfl_xor_sync(0xFFFFFFFFu, a.w, 16);
        if (half == 0) {
            a.x = fmaxf(a.x, 0.f);
            a.y = fmaxf(a.y, 0.f);
            a.z = fmaxf(a.z, 0.f);
            a.w = fmaxf(a.w, 0.f);
            uint32_t h01, l01, h23, l23;
            split_pair(a.x, a.y, h01, l01);
            split_pair(a.z, a.w, h23, l23);
            uint32_t* dh = (uint32_t*)&Ah[row * FST + l];
            uint32_t* dl = (uint32_t*)&Al[row * FST + l];
            dh[0] = h01; dh[1] = h23;
            dl[0] = l01; dl[1] = l23;
        }
    }
    __syncthreads();

    // phase 2: 64x64x64 HMMA (warps 0-3)
    if (wid < 4) {
        int gid = lane >> 2;
        int q = lane & 3;
        int rb = wid * 16;
        int g8 = lane >> 3, lr = lane & 7;
        int aoff = (rb + lr + (g8 & 1) * 8) * FST + (g8 >> 1) * 8;
        int boff0 = (lr + (g8 >> 1) * 8) * FST + (g8 & 1) * 8;
        uint32_t ah_b = smem_u32(Ah), al_b = smem_u32(Al);
        uint32_t bh_b = smem_u32(Bh), bl_b = smem_u32(Bl);

        float acc[8][4];
#pragma unroll
        for (int t = 0; t < 8; t++)
#pragma unroll
            for (int c = 0; c < 4; c++) acc[t][c] = 0.f;

#pragma unroll
        for (int s = 0; s < 4; s++) {
            uint32_t ah[4], al[4];
            ldsm_x4(ah[0], ah[1], ah[2], ah[3], ah_b + 2 * (aoff + s * 16));
            ldsm_x4(al[0], al[1], al[2], al[3], al_b + 2 * (aoff + s * 16));
#pragma unroll
            for (int p = 0; p < 4; p++) {
                int bo = boff0 + p * 16 * FST + s * 16;
                uint32_t bh[4], bl[4];
                ldsm_x4(bh[0], bh[1], bh[2], bh[3], bh_b + 2 * bo);
                ldsm_x4(bl[0], bl[1], bl[2], bl[3], bl_b + 2 * bo);
                int t0 = 2 * p, t1 = 2 * p + 1;
                mma_bf16(acc[t0][0], acc[t0][1], acc[t0][2], acc[t0][3],
                         ah[0], ah[1], ah[2], ah[3], bh[0], bh[1]);
                mma_bf16(acc[t0][0], acc[t0][1], acc[t0][2], acc[t0][3],
                         ah[0], ah[1], ah[2], ah[3], bl[0], bl[1]);
                mma_bf16(acc[t0][0], acc[t0][1], acc[t0][2], acc[t0][3],
                         al[0], al[1], al[2], al[3], bh[0], bh[1]);
                mma_bf16(acc[t1][0], acc[t1][1], acc[t1][2], acc[t1][3],
                         ah[0], ah[1], ah[2], ah[3], bh[2], bh[3]);
                mma_bf16(acc[t1][0], acc[t1][1], acc[t1][2], acc[t1][3],
                         ah[0], ah[1], ah[2], ah[3], bl[2], bl[3]);
                mma_bf16(acc[t1][0], acc[t1][1], acc[t1][2], acc[t1][3],
                         al[0], al[1], al[2], al[3], bh[2], bh[3]);
            }
        }

        int gr0 = r0 + rb + gid;
        int gr1 = gr0 + 8;
#pragma unroll
        for (int nt = 0; nt < 8; nt++) {
            int col = nt * 8 + 2 * q;
            if (gr0 < NN)
                *(float2*)(g_h2 + (size_t)gr0 * HID + col) =
                    make_float2(acc[nt][0], acc[nt][1]);
            if (gr1 < NN)
                *(float2*)(g_h2 + (size_t)gr1 * HID + col) =
                    make_float2(acc[nt][2], acc[nt][3]);
        }
    }
}

// ------- final aggregation (layer 2): warp per node, half-warp per edge -----
__global__ void k_agg(const float* __restrict__ H, const float* __restrict__ bias,
                      float* __restrict__ OUT, int do_relu) {
    int node = (blockIdx.x * blockDim.x + threadIdx.x) >> 5;
    if (node >= NN) return;
    int lane = threadIdx.x & 31;
    int half = lane >> 4;
    int l = (lane & 15) * 4;

    float di = g_dinv[node];
    float4 a = make_float4(0.f, 0.f, 0.f, 0.f);
    if (half == 0) {
        float sw = di * di;
        float4 hv = *(const float4*)(H + (size_t)node * HID + l);
        float4 b = *(const float4*)(bias + l);
        a.x = hv.x * sw + b.x;
        a.y = hv.y * sw + b.y;
        a.z = hv.z * sw + b.z;
        a.w = hv.w * sw + b.w;
    }
    int e1 = g_off[node + 1];
    for (int e = g_off[node] + half; e < e1; e += 2) {
        int s = g_csrc[e];
        float w = g_dinv[s] * di;
        float4 v = *(const float4*)(H + (size_t)s * HID + l);
        a.x += v.x * w;
        a.y += v.y * w;
        a.z += v.z * w;
        a.w += v.w * w;
    }
    a.x += __shfl_xor_sync(0xFFFFFFFFu, a.x, 16);
    a.y += __shfl_xor_sync(0xFFFFFFFFu, a.y, 16);
    a.z += __shfl_xor_sync(0xFFFFFFFFu, a.z, 16);
    a.w += __shfl_xor_sync(0xFFFFFFFFu, a.w, 16);
    if (half == 0) {
        if (do_relu) {
            a.x = fmaxf(a.x, 0.f);
            a.y = fmaxf(a.y, 0.f);
            a.z = fmaxf(a.z, 0.f);
            a.w = fmaxf(a.w, 0.f);
        }
        *(float4*)(OUT + (size_t)node * HID + l) = a;
    }
}

extern "C" void kernel_launch(void* const* d_in, const int* in_sizes, int n_in,
                              void* d_out, int out_size) {
    const float* x  = (const float*)d_in[0];
    const int*   ei = (const int*)d_in[1];   // [2, E]: src row then dst row
    const float* W1 = (const float*)d_in[2];
    const float* b1 = (const float*)d_in[3];
    const float* W2 = (const float*)d_in[4];
    const float* b2 = (const float*)d_in[5];
    float* out = (float*)d_out;
    const int* src = ei;
    const int* dst = ei + EE;

    float *ph, *ph2;
    uint16_t *w1h, *w1l;
    cudaGetSymbolAddress((void**)&ph, g_h);
    cudaGetSymbolAddress((void**)&ph2, g_h2);
    cudaGetSymbolAddress((void**)&w1h, g_wt1h);
    cudaGetSymbolAddress((void**)&w1l, g_wt1l);

    cudaFuncSetAttribute(k_scan, cudaFuncAttributeMaxDynamicSharedMemorySize,
                         NN * (int)sizeof(int));

    // Serial pipeline (stream fork regressed — L2 contention)
    k_prep<<<36, 256>>>(W1, W2);
    k_hist<<<(EE / 4 + 255) / 256, 256>>>(dst);      // g_cnt zeroed by prior k_fill
    k_scan<<<1, 1024, NN * sizeof(int)>>>();
    k_fill<<<(EE / 4 + 255) / 256, 256>>>(src, dst); // re-zeros g_cnt at the end

    // Layer 1 GEMM
    k_gemm<<<(NN + 63) / 64, 128>>>(x, w1h, w1l, ph, NN, 512);
    // Fused agg1 + relu + GEMM2
    k_fagg<<<(NN + 63) / 64, 256>>>(ph, b1);
    // Layer 2 aggregation
    k_agg<<<(NN * 32 + 255) / 256, 256>>>(ph2, b2, out, 0);
}

// round 11
// speedup vs baseline: 1.0355x; 1.0355x over previous
#include <cuda_runtime.h>
#include <cuda_bf16.h>
#include <cstdint>

#define NN 50000
#define EE 800000
#define HID 64

// ---------------- scratch (__device__ globals; no allocs allowed) ----------
__device__ float g_h[NN * HID];
__device__ float g_act[NN * HID];
__device__ int   g_cnt[NN];     // zero at load; re-zeroed by k_fill each run
__device__ int   g_off[NN + 1];
__device__ int   g_cur[NN];
__device__ float g_dinv[NN];
__device__ int   g_csrc[EE];
// Pre-transposed, bf16-split weights: Wt[n][k] (k contiguous)
__device__ uint16_t g_wt1h[64 * 512];
__device__ uint16_t g_wt1l[64 * 512];
__device__ uint16_t g_wt2h[64 * 64];
__device__ uint16_t g_wt2l[64 * 64];

// ---------------- helpers ---------------------------------------------------
__device__ __forceinline__ uint32_t smem_u32(const void* p) {
    uint32_t a;
    asm("{ .reg .u64 t; cvta.to.shared.u64 t, %1; cvt.u32.u64 %0, t; }"
        : "=r"(a) : "l"(p));
    return a;
}
__device__ __forceinline__ uint32_t cvt_bf16x2(float hi_elem, float lo_elem) {
    uint32_t r;
    asm("cvt.rn.bf16x2.f32 %0, %1, %2;" : "=r"(r) : "f"(hi_elem), "f"(lo_elem));
    return r;
}
__device__ __forceinline__ void split_pair(float x0, float x1,
                                           uint32_t& h, uint32_t& l) {
    h = cvt_bf16x2(x1, x0);
    float h0 = __uint_as_float(h << 16);
    float h1 = __uint_as_float(h & 0xffff0000u);
    l = cvt_bf16x2(x1 - h1, x0 - h0);
}
__device__ __forceinline__ void mma_bf16(float& d0, float& d1, float& d2, float& d3,
                                         uint32_t a0, uint32_t a1, uint32_t a2, uint32_t a3,
                                         uint32_t b0, uint32_t b1) {
    asm volatile("mma.sync.aligned.m16n8k16.row.col.f32.bf16.bf16.f32 "
                 "{%0,%1,%2,%3}, {%4,%5,%6,%7}, {%8,%9}, {%0,%1,%2,%3};"
                 : "+f"(d0), "+f"(d1), "+f"(d2), "+f"(d3)
                 : "r"(a0), "r"(a1), "r"(a2), "r"(a3), "r"(b0), "r"(b1));
}
__device__ __forceinline__ void ldsm_x4(uint32_t& r0, uint32_t& r1,
                                        uint32_t& r2, uint32_t& r3, uint32_t addr) {
    asm volatile("ldmatrix.sync.aligned.m8n8.x4.shared.b16 {%0,%1,%2,%3}, [%4];"
                 : "=r"(r0), "=r"(r1), "=r"(r2), "=r"(r3) : "r"(addr));
}

// ---------------- CSR construction -----------------------------------------
__global__ void k_hist(const int* __restrict__ dst) {
    int e = blockIdx.x * blockDim.x + threadIdx.x;
    if (e < EE) atomicAdd(&g_cnt[dst[e]], 1);
}

__global__ void k_scan() {
    extern __shared__ int buf[];
    __shared__ int sm[1024];
    int t = threadIdx.x;
    for (int i = t; i < NN; i += 1024) buf[i] = g_cnt[i];
    __syncthreads();
    const int C = (NN + 1023) / 1024;
    int start = t * C, end = start + C;
    if (end > NN) end = NN;
    int sum = 0;
    for (int i = start; i < end; i++) sum += buf[i];
    sm[t] = sum;
    __syncthreads();
    for (int ofs = 1; ofs < 1024; ofs <<= 1) {
        int v = (t >= ofs) ? sm[t - ofs] : 0;
        __syncthreads();
        sm[t] += v;
        __syncthreads();
    }
    int base = sm[t] - sum;
    for (int i = start; i < end; i++) {
        int c = buf[i];
        buf[i] = base;
        base += c;
        g_dinv[i] = rsqrtf((float)(c + 1));
    }
    __syncthreads();
    for (int i = t; i < NN; i += 1024) {
        int o = buf[i];
        g_off[i] = o;
        g_cur[i] = o;
    }
    if (t == 0) g_off[NN] = EE;
}

// fill CSR; also re-zero g_cnt for the next graph replay (cnt is dead here)
__global__ void k_fill(const int* __restrict__ src, const int* __restrict__ dst) {
    int e = blockIdx.x * blockDim.x + threadIdx.x;
    if (e < NN) g_cnt[e] = 0;
    if (e >= EE) return;
    int s = src[e], d = dst[e];
    int pos = atomicAdd(&g_cur[d], 1);
    g_csrc[pos] = s;
}

// ------- weight prep: coalesced smem-tile transpose + bf16 split ------------
__global__ void k_prep(const float* __restrict__ W1, const float* __restrict__ W2) {
    __shared__ uint16_t th[32][33], tl[32][33];
    int b = blockIdx.x;
    int tx = threadIdx.x & 31, ty = threadIdx.x >> 5;

    const float* W;
    uint16_t *oh, *ol;
    int kt, ntile, Kd;
    if (b < 32) { W = W1; oh = g_wt1h; ol = g_wt1l; kt = b >> 1; ntile = b & 1; Kd = 512; }
    else        { W = W2; oh = g_wt2h; ol = g_wt2l; kt = (b - 32) >> 1; ntile = (b - 32) & 1; Kd = 64; }

#pragma unroll
    for (int j = 0; j < 4; j++) {
        int k = kt * 32 + ty + j * 8;
        int n = ntile * 32 + tx;
        float v = W[k * 64 + n];
        uint16_t hs = __bfloat16_as_ushort(__float2bfloat16(v));
        float hf = __uint_as_float((uint32_t)hs << 16);
        uint16_t ls = __bfloat16_as_ushort(__float2bfloat16(v - hf));
        th[ty + j * 8][tx] = hs;
        tl[ty + j * 8][tx] = ls;
    }
    __syncthreads();
#pragma unroll
    for (int j = 0; j < 4; j++) {
        int n = ntile * 32 + ty + j * 8;
        int k = kt * 32 + tx;
        oh[n * Kd + k] = th[tx][ty + j * 8];
        ol[n * Kd + k] = tl[tx][ty + j * 8];
    }
}

// ---------------- HMMA bf16-split GEMM (ldmatrix fragments) -----------------
#define XST 40   // smem row stride (uint16): 80B = 5*16B -> LDSM conflict-free

__global__ __launch_bounds__(128, 4) void k_gemm(
    const float* __restrict__ X,
    const uint16_t* __restrict__ Wth, const uint16_t* __restrict__ Wtl,
    float* __restrict__ OUT, int n, int Kdim) {
    __shared__ __align__(16) uint16_t Xh[64 * XST], Xl[64 * XST];
    __shared__ __align__(16) uint16_t Wh[64 * XST], Wl[64 * XST];
    int tid = threadIdx.x;
    int wid = tid >> 5;
    int lane = tid & 31;
    int gid = lane >> 2;
    int q = lane & 3;
    int r0 = blockIdx.x * 64;
    int rb = wid * 16;

    int xrow = tid >> 3;
    int xkg = (tid & 7) * 4;
    int wn = tid >> 4;
    int wkg = tid & 15;

    int g8 = lane >> 3, lr = lane & 7;
    int aoff = (rb + lr + (g8 & 1) * 8) * XST + (g8 >> 1) * 8;
    int boff0 = (lr + (g8 >> 1) * 8) * XST + (g8 & 1) * 8;
    uint32_t xh_b = smem_u32(Xh), xl_b = smem_u32(Xl);
    uint32_t wh_b = smem_u32(Wh), wl_b = smem_u32(Wl);

    const uint32_t* wh32 = (const uint32_t*)Wth;
    const uint32_t* wl32 = (const uint32_t*)Wtl;
    int wstride = Kdim >> 1;

    float acc[8][4];
#pragma unroll
    for (int t = 0; t < 8; t++)
#pragma unroll
        for (int c = 0; c < 4; c++) acc[t][c] = 0.f;

    int nch = Kdim >> 5;
    float4 px[4];
    uint32_t pwh[8], pwl[8];

#pragma unroll
    for (int j = 0; j < 4; j++) {
        int gr = r0 + xrow + j * 16;
        px[j] = (gr < n) ? *(const float4*)(X + (size_t)gr * Kdim + xkg)
                         : make_float4(0.f, 0.f, 0.f, 0.f);
    }
#pragma unroll
    for (int j = 0; j < 8; j++) {
        int nn = wn + j * 8;
        pwh[j] = wh32[nn * wstride + wkg];
        pwl[j] = wl32[nn * wstride + wkg];
    }

    for (int ch = 0; ch < nch; ch++) {
#pragma unroll
        for (int j = 0; j < 4; j++) {
            int row = xrow + j * 16;
            uint32_t h01, l01, h23, l23;
            split_pair(px[j].x, px[j].y, h01, l01);
            split_pair(px[j].z, px[j].w, h23, l23);
            uint32_t* dh = (uint32_t*)&Xh[row * XST + xkg];
            uint32_t* dl = (uint32_t*)&Xl[row * XST + xkg];
            dh[0] = h01; dh[1] = h23;
            dl[0] = l01; dl[1] = l23;
        }
#pragma unroll
        for (int j = 0; j < 8; j++) {
            int nn = wn + j * 8;
            *(uint32_t*)&Wh[nn * XST + wkg * 2] = pwh[j];
            *(uint32_t*)&Wl[nn * XST + wkg * 2] = pwl[j];
        }
        __syncthreads();

        if (ch + 1 < nch) {
            int k0 = (ch + 1) << 5;
#pragma unroll
            for (int j = 0; j < 4; j++) {
                int gr = r0 + xrow + j * 16;
                px[j] = (gr < n)
                    ? *(const float4*)(X + (size_t)gr * Kdim + k0 + xkg)
                    : make_float4(0.f, 0.f, 0.f, 0.f);
            }
#pragma unroll
            for (int j = 0; j < 8; j++) {
                int nn = wn + j * 8;
                pwh[j] = wh32[nn * wstride + (k0 >> 1) + wkg];
                pwl[j] = wl32[nn * wstride + (k0 >> 1) + wkg];
            }
        }

#pragma unroll
        for (int s = 0; s < 2; s++) {
            uint32_t ah[4], al[4];
            ldsm_x4(ah[0], ah[1], ah[2], ah[3], xh_b + 2 * (aoff + s * 16));
            ldsm_x4(al[0], al[1], al[2], al[3], xl_b + 2 * (aoff + s * 16));
#pragma unroll
            for (int p = 0; p < 4; p++) {
                int bo = boff0 + p * 16 * XST + s * 16;
                uint32_t bh[4], bl[4];
                ldsm_x4(bh[0], bh[1], bh[2], bh[3], wh_b + 2 * bo);
                ldsm_x4(bl[0], bl[1], bl[2], bl[3], wl_b + 2 * bo);
                int t0 = 2 * p, t1 = 2 * p + 1;
                mma_bf16(acc[t0][0], acc[t0][1], acc[t0][2], acc[t0][3],
                         ah[0], ah[1], ah[2], ah[3], bh[0], bh[1]);
                mma_bf16(acc[t0][0], acc[t0][1], acc[t0][2], acc[t0][3],
                         ah[0], ah[1], ah[2], ah[3], bl[0], bl[1]);
                mma_bf16(acc[t0][0], acc[t0][1], acc[t0][2], acc[t0][3],
                         al[0], al[1], al[2], al[3], bh[0], bh[1]);
                mma_bf16(acc[t1][0], acc[t1][1], acc[t1][2], acc[t1][3],
                         ah[0], ah[1], ah[2], ah[3], bh[2], bh[3]);
                mma_bf16(acc[t1][0], acc[t1][1], acc[t1][2], acc[t1][3],
                         ah[0], ah[1], ah[2], ah[3], bl[2], bl[3]);
                mma_bf16(acc[t1][0], acc[t1][1], acc[t1][2], acc[t1][3],
                         al[0], al[1], al[2], al[3], bh[2], bh[3]);
            }
        }
        __syncthreads();
    }

    int gr0 = r0 + rb + gid;
    int gr1 = gr0 + 8;
#pragma unroll
    for (int nt = 0; nt < 8; nt++) {
        int col = nt * 8 + 2 * q;
        if (gr0 < n)
            *(float2*)(OUT + (size_t)gr0 * HID + col) =
                make_float2(acc[nt][0], acc[nt][1]);
        if (gr1 < n)
            *(float2*)(OUT + (size_t)gr1 * HID + col) =
                make_float2(acc[nt][2], acc[nt][3]);
    }
}

// ------- gather aggregation: warp per node, half-warp per edge, float4 ------
// Edge loop unrolled x2 with independent row loads -> MLP 2 on L2 gathers.
__global__ void k_agg(const float* __restrict__ H, const float* __restrict__ bias,
                      float* __restrict__ OUT, int do_relu) {
    int node = (blockIdx.x * blockDim.x + threadIdx.x) >> 5;
    if (node >= NN) return;
    int lane = threadIdx.x & 31;
    int half = lane >> 4;          // 0 or 1
    int l = (lane & 15) * 4;       // feature offset (float4)

    float di = g_dinv[node];
    float4 a = make_float4(0.f, 0.f, 0.f, 0.f);
    if (half == 0) {
        float sw = di * di;
        float4 hv = *(const float4*)(H + (size_t)node * HID + l);
        float4 b = *(const float4*)(bias + l);
        a.x = hv.x * sw + b.x;
        a.y = hv.y * sw + b.y;
        a.z = hv.z * sw + b.z;
        a.w = hv.w * sw + b.w;
    }

    int e = g_off[node] + half;
    int e1 = g_off[node + 1];
    // unrolled x2: two independent gathers in flight
    for (; e + 2 < e1; e += 4) {
        int s0 = g_csrc[e];
        int s1 = g_csrc[e + 2];
        float w0 = g_dinv[s0] * di;
        float w1 = g_dinv[s1] * di;
        float4 v0 = *(const float4*)(H + (size_t)s0 * HID + l);
        float4 v1 = *(const float4*)(H + (size_t)s1 * HID + l);
        a.x += v0.x * w0; a.y += v0.y * w0; a.z += v0.z * w0; a.w += v0.w * w0;
        a.x += v1.x * w1; a.y += v1.y * w1; a.z += v1.z * w1; a.w += v1.w * w1;
    }
    for (; e < e1; e += 2) {
        int s = g_csrc[e];
        float w = g_dinv[s] * di;
        float4 v = *(const float4*)(H + (size_t)s * HID + l);
        a.x += v.x * w; a.y += v.y * w; a.z += v.z * w; a.w += v.w * w;
    }
    // merge halves
    a.x += __shfl_xor_sync(0xFFFFFFFFu, a.x, 16);
    a.y += __shfl_xor_sync(0xFFFFFFFFu, a.y, 16);
    a.z += __shfl_xor_sync(0xFFFFFFFFu, a.z, 16);
    a.w += __shfl_xor_sync(0xFFFFFFFFu, a.w, 16);

    if (half == 0) {
        if (do_relu) {
            a.x = fmaxf(a.x, 0.f);
            a.y = fmaxf(a.y, 0.f);
            a.z = fmaxf(a.z, 0.f);
            a.w = fmaxf(a.w, 0.f);
        }
        *(float4*)(OUT + (size_t)node * HID + l) = a;
    }
}

extern "C" void kernel_launch(void* const* d_in, const int* in_sizes, int n_in,
                              void* d_out, int out_size) {
    const float* x  = (const float*)d_in[0];
    const int*   ei = (const int*)d_in[1];   // [2, E]: src row then dst row
    const float* W1 = (const float*)d_in[2];
    const float* b1 = (const float*)d_in[3];
    const float* W2 = (const float*)d_in[4];
    const float* b2 = (const float*)d_in[5];
    float* out = (float*)d_out;
    const int* src = ei;
    const int* dst = ei + EE;

    float *ph, *pact;
    uint16_t *w1h, *w1l, *w2h, *w2l;
    cudaGetSymbolAddress((void**)&ph, g_h);
    cudaGetSymbolAddress((void**)&pact, g_act);
    cudaGetSymbolAddress((void**)&w1h, g_wt1h);
    cudaGetSymbolAddress((void**)&w1l, g_wt1l);
    cudaGetSymbolAddress((void**)&w2h, g_wt2h);
    cudaGetSymbolAddress((void**)&w2l, g_wt2l);

    cudaFuncSetAttribute(k_scan, cudaFuncAttributeMaxDynamicSharedMemorySize,
                         NN * (int)sizeof(int));

    // Serial pipeline (stream fork regressed — L2 contention)
    k_prep<<<36, 256>>>(W1, W2);
    k_hist<<<(EE + 255) / 256, 256>>>(dst);      // g_cnt zeroed by prior k_fill
    k_scan<<<1, 1024, NN * sizeof(int)>>>();
    k_fill<<<(EE + 255) / 256, 256>>>(src, dst); // re-zeros g_cnt at the end

    // Layer 1
    k_gemm<<<(NN + 63) / 64, 128>>>(x, w1h, w1l, ph, NN, 512);
    k_agg<<<(NN * 32 + 255) / 256, 256>>>(ph, b1, pact, 1);
    // Layer 2
    k_gemm<<<(NN + 63) / 64, 128>>>(pact, w2h, w2l, ph, NN, HID);
    k_agg<<<(NN * 32 + 255) / 256, 256>>>(ph, b2, out, 0);
}

// round 12
// speedup vs baseline: 1.0388x; 1.0032x over previous
#include <cuda_runtime.h>
#include <cuda_bf16.h>
#include <cuda_fp16.h>
#include <cstdint>

#define NN 50000
#define EE 800000
#define HID 64

// ---------------- scratch (__device__ globals; no allocs allowed) ----------
__device__ __half g_h[NN * HID];    // gemm output (fp16) — gather source
__device__ float  g_act[NN * HID];  // layer-1 activations (fp32, feeds gemm2)
__device__ int    g_cnt[NN];        // zero at load; re-zeroed by k_fill each run
__device__ int    g_off[NN + 1];
__device__ int    g_cur[NN];
__device__ float  g_dinv[NN];
__device__ int    g_csrc[EE];
// Pre-transposed, bf16-split weights: Wt[n][k] (k contiguous)
__device__ uint16_t g_wt1h[64 * 512];
__device__ uint16_t g_wt1l[64 * 512];
__device__ uint16_t g_wt2h[64 * 64];
__device__ uint16_t g_wt2l[64 * 64];

// ---------------- helpers ---------------------------------------------------
__device__ __forceinline__ uint32_t smem_u32(const void* p) {
    uint32_t a;
    asm("{ .reg .u64 t; cvta.to.shared.u64 t, %1; cvt.u32.u64 %0, t; }"
        : "=r"(a) : "l"(p));
    return a;
}
__device__ __forceinline__ uint32_t cvt_bf16x2(float hi_elem, float lo_elem) {
    uint32_t r;
    asm("cvt.rn.bf16x2.f32 %0, %1, %2;" : "=r"(r) : "f"(hi_elem), "f"(lo_elem));
    return r;
}
__device__ __forceinline__ void split_pair(float x0, float x1,
                                           uint32_t& h, uint32_t& l) {
    h = cvt_bf16x2(x1, x0);
    float h0 = __uint_as_float(h << 16);
    float h1 = __uint_as_float(h & 0xffff0000u);
    l = cvt_bf16x2(x1 - h1, x0 - h0);
}
__device__ __forceinline__ void mma_bf16(float& d0, float& d1, float& d2, float& d3,
                                         uint32_t a0, uint32_t a1, uint32_t a2, uint32_t a3,
                                         uint32_t b0, uint32_t b1) {
    asm volatile("mma.sync.aligned.m16n8k16.row.col.f32.bf16.bf16.f32 "
                 "{%0,%1,%2,%3}, {%4,%5,%6,%7}, {%8,%9}, {%0,%1,%2,%3};"
                 : "+f"(d0), "+f"(d1), "+f"(d2), "+f"(d3)
                 : "r"(a0), "r"(a1), "r"(a2), "r"(a3), "r"(b0), "r"(b1));
}
__device__ __forceinline__ void ldsm_x4(uint32_t& r0, uint32_t& r1,
                                        uint32_t& r2, uint32_t& r3, uint32_t addr) {
    asm volatile("ldmatrix.sync.aligned.m8n8.x4.shared.b16 {%0,%1,%2,%3}, [%4];"
                 : "=r"(r0), "=r"(r1), "=r"(r2), "=r"(r3) : "r"(addr));
}

// --------- merged: histogram (blocks 0..3124) + weight prep (3125..3160) ----
__global__ void k_hist_prep(const int* __restrict__ dst,
                            const float* __restrict__ W1,
                            const float* __restrict__ W2) {
    __shared__ uint16_t th[32][33], tl[32][33];
    int b = blockIdx.x;
    if (b < EE / 256) {
        int e = b * 256 + threadIdx.x;
        atomicAdd(&g_cnt[dst[e]], 1);   // EE divisible by 256
        return;
    }
    int bb = b - EE / 256;              // 0..35
    int tx = threadIdx.x & 31, ty = threadIdx.x >> 5;
    const float* W;
    uint16_t *oh, *ol;
    int kt, ntile, Kd;
    if (bb < 32) { W = W1; oh = g_wt1h; ol = g_wt1l; kt = bb >> 1; ntile = bb & 1; Kd = 512; }
    else         { W = W2; oh = g_wt2h; ol = g_wt2l; kt = (bb - 32) >> 1; ntile = (bb - 32) & 1; Kd = 64; }
#pragma unroll
    for (int j = 0; j < 4; j++) {
        int k = kt * 32 + ty + j * 8;
        int n = ntile * 32 + tx;
        float v = W[k * 64 + n];
        uint16_t hs = __bfloat16_as_ushort(__float2bfloat16(v));
        float hf = __uint_as_float((uint32_t)hs << 16);
        uint16_t ls = __bfloat16_as_ushort(__float2bfloat16(v - hf));
        th[ty + j * 8][tx] = hs;
        tl[ty + j * 8][tx] = ls;
    }
    __syncthreads();
#pragma unroll
    for (int j = 0; j < 4; j++) {
        int n = ntile * 32 + ty + j * 8;
        int k = kt * 32 + tx;
        oh[n * Kd + k] = th[tx][ty + j * 8];
        ol[n * Kd + k] = tl[tx][ty + j * 8];
    }
}

__global__ void k_scan() {
    extern __shared__ int buf[];
    __shared__ int sm[1024];
    int t = threadIdx.x;
    for (int i = t; i < NN; i += 1024) buf[i] = g_cnt[i];
    __syncthreads();
    const int C = (NN + 1023) / 1024;
    int start = t * C, end = start + C;
    if (end > NN) end = NN;
    int sum = 0;
    for (int i = start; i < end; i++) sum += buf[i];
    sm[t] = sum;
    __syncthreads();
    for (int ofs = 1; ofs < 1024; ofs <<= 1) {
        int v = (t >= ofs) ? sm[t - ofs] : 0;
        __syncthreads();
        sm[t] += v;
        __syncthreads();
    }
    int base = sm[t] - sum;
    for (int i = start; i < end; i++) {
        int c = buf[i];
        buf[i] = base;
        base += c;
        g_dinv[i] = rsqrtf((float)(c + 1));
    }
    __syncthreads();
    for (int i = t; i < NN; i += 1024) {
        int o = buf[i];
        g_off[i] = o;
        g_cur[i] = o;
    }
    if (t == 0) g_off[NN] = EE;
}

// fill CSR; also re-zero g_cnt for the next graph replay (cnt is dead here)
__global__ void k_fill(const int* __restrict__ src, const int* __restrict__ dst) {
    int e = blockIdx.x * blockDim.x + threadIdx.x;
    if (e < NN) g_cnt[e] = 0;
    if (e >= EE) return;
    int s = src[e], d = dst[e];
    int pos = atomicAdd(&g_cur[d], 1);
    g_csrc[pos] = s;
}

// ---------------- HMMA bf16-split GEMM (ldmatrix fragments) -----------------
// OUT is fp16 (NN x 64). Accumulation fp32 in registers; store rounds to fp16.
#define XST 40   // smem row stride (uint16): 80B = 5*16B -> LDSM conflict-free

__global__ __launch_bounds__(128, 4) void k_gemm(
    const float* __restrict__ X,
    const uint16_t* __restrict__ Wth, const uint16_t* __restrict__ Wtl,
    __half* __restrict__ OUT, int n, int Kdim) {
    __shared__ __align__(16) uint16_t Xh[64 * XST], Xl[64 * XST];
    __shared__ __align__(16) uint16_t Wh[64 * XST], Wl[64 * XST];
    int tid = threadIdx.x;
    int wid = tid >> 5;
    int lane = tid & 31;
    int gid = lane >> 2;
    int q = lane & 3;
    int r0 = blockIdx.x * 64;
    int rb = wid * 16;

    int xrow = tid >> 3;
    int xkg = (tid & 7) * 4;
    int wn = tid >> 4;
    int wkg = tid & 15;

    int g8 = lane >> 3, lr = lane & 7;
    int aoff = (rb + lr + (g8 & 1) * 8) * XST + (g8 >> 1) * 8;
    int boff0 = (lr + (g8 >> 1) * 8) * XST + (g8 & 1) * 8;
    uint32_t xh_b = smem_u32(Xh), xl_b = smem_u32(Xl);
    uint32_t wh_b = smem_u32(Wh), wl_b = smem_u32(Wl);

    const uint32_t* wh32 = (const uint32_t*)Wth;
    const uint32_t* wl32 = (const uint32_t*)Wtl;
    int wstride = Kdim >> 1;

    float acc[8][4];
#pragma unroll
    for (int t = 0; t < 8; t++)
#pragma unroll
        for (int c = 0; c < 4; c++) acc[t][c] = 0.f;

    int nch = Kdim >> 5;
    float4 px[4];
    uint32_t pwh[8], pwl[8];

#pragma unroll
    for (int j = 0; j < 4; j++) {
        int gr = r0 + xrow + j * 16;
        px[j] = (gr < n) ? *(const float4*)(X + (size_t)gr * Kdim + xkg)
                         : make_float4(0.f, 0.f, 0.f, 0.f);
    }
#pragma unroll
    for (int j = 0; j < 8; j++) {
        int nn = wn + j * 8;
        pwh[j] = wh32[nn * wstride + wkg];
        pwl[j] = wl32[nn * wstride + wkg];
    }

    for (int ch = 0; ch < nch; ch++) {
#pragma unroll
        for (int j = 0; j < 4; j++) {
            int row = xrow + j * 16;
            uint32_t h01, l01, h23, l23;
            split_pair(px[j].x, px[j].y, h01, l01);
            split_pair(px[j].z, px[j].w, h23, l23);
            uint32_t* dh = (uint32_t*)&Xh[row * XST + xkg];
            uint32_t* dl = (uint32_t*)&Xl[row * XST + xkg];
            dh[0] = h01; dh[1] = h23;
            dl[0] = l01; dl[1] = l23;
        }
#pragma unroll
        for (int j = 0; j < 8; j++) {
            int nn = wn + j * 8;
            *(uint32_t*)&Wh[nn * XST + wkg * 2] = pwh[j];
            *(uint32_t*)&Wl[nn * XST + wkg * 2] = pwl[j];
        }
        __syncthreads();

        if (ch + 1 < nch) {
            int k0 = (ch + 1) << 5;
#pragma unroll
            for (int j = 0; j < 4; j++) {
                int gr = r0 + xrow + j * 16;
                px[j] = (gr < n)
                    ? *(const float4*)(X + (size_t)gr * Kdim + k0 + xkg)
                    : make_float4(0.f, 0.f, 0.f, 0.f);
            }
#pragma unroll
            for (int j = 0; j < 8; j++) {
                int nn = wn + j * 8;
                pwh[j] = wh32[nn * wstride + (k0 >> 1) + wkg];
                pwl[j] = wl32[nn * wstride + (k0 >> 1) + wkg];
            }
        }

#pragma unroll
        for (int s = 0; s < 2; s++) {
            uint32_t ah[4], al[4];
            ldsm_x4(ah[0], ah[1], ah[2], ah[3], xh_b + 2 * (aoff + s * 16));
            ldsm_x4(al[0], al[1], al[2], al[3], xl_b + 2 * (aoff + s * 16));
#pragma unroll
            for (int p = 0; p < 4; p++) {
                int bo = boff0 + p * 16 * XST + s * 16;
                uint32_t bh[4], bl[4];
                ldsm_x4(bh[0], bh[1], bh[2], bh[3], wh_b + 2 * bo);
                ldsm_x4(bl[0], bl[1], bl[2], bl[3], wl_b + 2 * bo);
                int t0 = 2 * p, t1 = 2 * p + 1;
                mma_bf16(acc[t0][0], acc[t0][1], acc[t0][2], acc[t0][3],
                         ah[0], ah[1], ah[2], ah[3], bh[0], bh[1]);
                mma_bf16(acc[t0][0], acc[t0][1], acc[t0][2], acc[t0][3],
                         ah[0], ah[1], ah[2], ah[3], bl[0], bl[1]);
                mma_bf16(acc[t0][0], acc[t0][1], acc[t0][2], acc[t0][3],
                         al[0], al[1], al[2], al[3], bh[0], bh[1]);
                mma_bf16(acc[t1][0], acc[t1][1], acc[t1][2], acc[t1][3],
                         ah[0], ah[1], ah[2], ah[3], bh[2], bh[3]);
                mma_bf16(acc[t1][0], acc[t1][1], acc[t1][2], acc[t1][3],
                         ah[0], ah[1], ah[2], ah[3], bl[2], bl[3]);
                mma_bf16(acc[t1][0], acc[t1][1], acc[t1][2], acc[t1][3],
                         al[0], al[1], al[2], al[3], bh[2], bh[3]);
            }
        }
        __syncthreads();
    }

    int gr0 = r0 + rb + gid;
    int gr1 = gr0 + 8;
#pragma unroll
    for (int nt = 0; nt < 8; nt++) {
        int col = nt * 8 + 2 * q;
        if (gr0 < n)
            *(__half2*)(OUT + (size_t)gr0 * HID + col) =
                __floats2half2_rn(acc[nt][0], acc[nt][1]);
        if (gr1 < n)
            *(__half2*)(OUT + (size_t)gr1 * HID + col) =
                __floats2half2_rn(acc[nt][2], acc[nt][3]);
    }
}

// ------- gather aggregation: warp per node, half-warp per edge, fp16 rows ---
// Each edge gather = one 128B line. fp32 accumulate, fp32 output.
__global__ void k_agg(const __half* __restrict__ H, const float* __restrict__ bias,
                      float* __restrict__ OUT, int do_relu) {
    int node = (blockIdx.x * blockDim.x + threadIdx.x) >> 5;
    if (node >= NN) return;
    int lane = threadIdx.x & 31;
    int half = lane >> 4;          // 0 or 1
    int l = (lane & 15) * 4;       // feature offset (4 halves = 8B per lane)

    float di = g_dinv[node];
    float4 a = make_float4(0.f, 0.f, 0.f, 0.f);
    if (half == 0) {
        float sw = di * di;
        uint2 raw = *(const uint2*)(H + (size_t)node * HID + l);
        float2 v01 = __half22float2(*(const __half2*)&raw.x);
        float2 v23 = __half22float2(*(const __half2*)&raw.y);
        float4 b = *(const float4*)(bias + l);
        a.x = v01.x * sw + b.x;
        a.y = v01.y * sw + b.y;
        a.z = v23.x * sw + b.z;
        a.w = v23.y * sw + b.w;
    }

    int e = g_off[node] + half;
    int e1 = g_off[node + 1];
    for (; e + 2 < e1; e += 4) {
        int s0 = g_csrc[e];
        int s1 = g_csrc[e + 2];
        float w0 = g_dinv[s0] * di;
        float w1 = g_dinv[s1] * di;
        uint2 r0 = *(const uint2*)(H + (size_t)s0 * HID + l);
        uint2 r1 = *(const uint2*)(H + (size_t)s1 * HID + l);
        float2 p0 = __half22float2(*(const __half2*)&r0.x);
        float2 p1 = __half22float2(*(const __half2*)&r0.y);
        float2 q0 = __half22float2(*(const __half2*)&r1.x);
        float2 q1 = __half22float2(*(const __half2*)&r1.y);
        a.x += p0.x * w0; a.y += p0.y * w0; a.z += p1.x * w0; a.w += p1.y * w0;
        a.x += q0.x * w1; a.y += q0.y * w1; a.z += q1.x * w1; a.w += q1.y * w1;
    }
    for (; e < e1; e += 2) {
        int s = g_csrc[e];
        float w = g_dinv[s] * di;
        uint2 r = *(const uint2*)(H + (size_t)s * HID + l);
        float2 p0 = __half22float2(*(const __half2*)&r.x);
        float2 p1 = __half22float2(*(const __half2*)&r.y);
        a.x += p0.x * w; a.y += p0.y * w; a.z += p1.x * w; a.w += p1.y * w;
    }
    // merge halves
    a.x += __shfl_xor_sync(0xFFFFFFFFu, a.x, 16);
    a.y += __shfl_xor_sync(0xFFFFFFFFu, a.y, 16);
    a.z += __shfl_xor_sync(0xFFFFFFFFu, a.z, 16);
    a.w += __shfl_xor_sync(0xFFFFFFFFu, a.w, 16);

    if (half == 0) {
        if (do_relu) {
            a.x = fmaxf(a.x, 0.f);
            a.y = fmaxf(a.y, 0.f);
            a.z = fmaxf(a.z, 0.f);
            a.w = fmaxf(a.w, 0.f);
        }
        *(float4*)(OUT + (size_t)node * HID + l) = a;
    }
}

extern "C" void kernel_launch(void* const* d_in, const int* in_sizes, int n_in,
                              void* d_out, int out_size) {
    const float* x  = (const float*)d_in[0];
    const int*   ei = (const int*)d_in[1];   // [2, E]: src row then dst row
    const float* W1 = (const float*)d_in[2];
    const float* b1 = (const float*)d_in[3];
    const float* W2 = (const float*)d_in[4];
    const float* b2 = (const float*)d_in[5];
    float* out = (float*)d_out;
    const int* src = ei;
    const int* dst = ei + EE;

    __half* ph;
    float* pact;
    uint16_t *w1h, *w1l, *w2h, *w2l;
    cudaGetSymbolAddress((void**)&ph, g_h);
    cudaGetSymbolAddress((void**)&pact, g_act);
    cudaGetSymbolAddress((void**)&w1h, g_wt1h);
    cudaGetSymbolAddress((void**)&w1l, g_wt1l);
    cudaGetSymbolAddress((void**)&w2h, g_wt2h);
    cudaGetSymbolAddress((void**)&w2l, g_wt2l);

    cudaFuncSetAttribute(k_scan, cudaFuncAttributeMaxDynamicSharedMemorySize,
                         NN * (int)sizeof(int));

    // Serial pipeline
    k_hist_prep<<<EE / 256 + 36, 256>>>(dst, W1, W2);   // hist + weight prep
    k_scan<<<1, 1024, NN * sizeof(int)>>>();
    k_fill<<<(EE + 255) / 256, 256>>>(src, dst);        // re-zeros g_cnt

    // Layer 1
    k_gemm<<<(NN + 63) / 64, 128>>>(x, w1h, w1l, ph, NN, 512);
    k_agg<<<(NN * 32 + 255) / 256, 256>>>(ph, b1, pact, 1);
    // Layer 2
    k_gemm<<<(NN + 63) / 64, 128>>>(pact, w2h, w2l, ph, NN, HID);
    k_agg<<<(NN * 32 + 255) / 256, 256>>>(ph, b2, out, 0);
}